// round 14
// baseline (speedup 1.0000x reference)
#include <cuda_runtime.h>
#include <cuda_fp16.h>
#include <cstdint>

// out[b,d,k] = sum_e S[k,d,e] * (x[b,e,k] - mu[e,k])
// B=8192, D=E=64, K=128. fp32 in/out.
// R14: 2-sync pipeline. Per sub-tile: MMA -> sync -> [stx(next) + Dbuf write]
// -> sync -> [LDS+STG + ldx(next+1)]. Single-pass 64KB Dbuf = A_cur (33KB) + E
// (33KB); all 16 warps participate in every phase; epilogue(i) overlaps
// MMA(i+1) across warps. Warp tile 2k x 16b x 32d (8 kq x 2 dh), KT=16.

#define NBY  18
#define ASTR 2064                         // per-k A stride (16 rows x 128B + pad)

static constexpr int ABUF = 16 * ASTR;    // 33024 per region
static constexpr int EOFF = 2 * ABUF;     // 66048 (epilogue region, 33024)
static constexpr int BOFF = 3 * ABUF;     // 99072
static constexpr int SMEM_BYTES = BOFF + 16 * 8192;   // 230144

__device__ __forceinline__ uint32_t cvt2(float hi, float lo) {
    uint32_t r;
    asm("cvt.rn.f16x2.f32 %0, %1, %2;" : "=r"(r) : "f"(hi), "f"(lo));
    return r;
}
__device__ __forceinline__ void ldm_x4(uint32_t& r0, uint32_t& r1, uint32_t& r2,
                                       uint32_t& r3, uint32_t addr) {
    asm volatile("ldmatrix.sync.aligned.m8n8.x4.shared.b16 {%0,%1,%2,%3}, [%4];"
                 : "=r"(r0), "=r"(r1), "=r"(r2), "=r"(r3) : "r"(addr));
}
__device__ __forceinline__ void ldm_x4t(uint32_t& r0, uint32_t& r1, uint32_t& r2,
                                        uint32_t& r3, uint32_t addr) {
    asm volatile("ldmatrix.sync.aligned.m8n8.x4.trans.shared.b16 {%0,%1,%2,%3}, [%4];"
                 : "=r"(r0), "=r"(r1), "=r"(r2), "=r"(r3) : "r"(addr));
}
__device__ __forceinline__ void mma16816(float& d0, float& d1, float& d2, float& d3,
                                         uint32_t a0, uint32_t a1, uint32_t a2, uint32_t a3,
                                         uint32_t b0, uint32_t b1) {
    asm volatile(
        "mma.sync.aligned.m16n8k16.row.col.f32.f16.f16.f32 "
        "{%0,%1,%2,%3}, {%4,%5,%6,%7}, {%8,%9}, {%0,%1,%2,%3};"
        : "+f"(d0), "+f"(d1), "+f"(d2), "+f"(d3)
        : "r"(a0), "r"(a1), "r"(a2), "r"(a3), "r"(b0), "r"(b1));
}

__global__ __launch_bounds__(512, 1)
void cluster_norm_mma_kernel(const float* __restrict__ x,
                             const float* __restrict__ mu,
                             const float* __restrict__ S,
                             float* __restrict__ out)
{
    extern __shared__ char smem[];
    const uint32_t sb = (uint32_t)__cvta_generic_to_shared(smem);
    const int tid   = threadIdx.x;
    const int lane  = tid & 31;
    const int w     = tid >> 5;
    const int kbase = blockIdx.x * 16;
    const int by    = blockIdx.y;

    // ---- S -> fp16 B tiles: Bk[e][d], rows 128B, slot ^= (e&7) ----
    #pragma unroll 4
    for (int i = 0; i < 64; i++) {
        int o  = tid + 512 * i;
        int e  = o & 63;
        int dp = (o >> 6) & 31;
        int k  = o >> 11;                 // 0..15
        const float* sp = S + (size_t)(kbase + k) * 4096 + (size_t)(dp * 2) * 64 + e;
        float s0 = sp[0];
        float s1 = sp[64];
        uint32_t h2 = cvt2(s1, s0);       // lo = even d
        uint32_t a = sb + BOFF + k * 8192 + e * 128
                   + ((((uint32_t)(dp >> 2)) ^ (uint32_t)(e & 7)) << 4) + (dp & 3) * 4;
        asm volatile("st.shared.b32 [%0], %1;" :: "r"(a), "r"(h2) : "memory");
    }

    // ---- phase-1 thread constants + mu register preload ----
    const int kq1   = tid & 3;            // k-quad for staging
    const int ep    = (tid >> 2) & 31;    // e-pair
    const int bloc0 = tid >> 7;           // 0..3
    float4 m0 = *(const float4*)(mu + (size_t)(2 * ep) * 128 + kbase + kq1 * 4);
    float4 m1 = *(const float4*)(mu + (size_t)(2 * ep + 1) * 128 + kbase + kq1 * 4);

    // warp tile: kq = w&7 (2 k), dh = w>>3 (32 d), all 16 b
    const int kq  = w & 7;
    const int dh  = w >> 3;
    const int l15 = lane & 15;
    const int lhi = lane >> 4;
    const int g   = lane >> 2;
    const int tg  = lane & 3;

    const uint32_t abase0 = sb;
    const uint32_t abase1 = sb + ABUF;

    float4 xr[4][2];

    auto ldx = [&](int bt) {
        const int b0 = bt * 16;
        #pragma unroll
        for (int i = 0; i < 4; i++) {
            const int b = bloc0 + 4 * i;
            const float* xp = x + (size_t)(b0 + b) * 8192 + (size_t)(2 * ep) * 128
                            + kbase + kq1 * 4;
            xr[i][0] = *(const float4*)(xp);        // e = 2ep
            xr[i][1] = *(const float4*)(xp + 128);  // e = 2ep+1
        }
    };
    auto stx = [&](uint32_t abase) {
        #pragma unroll
        for (int i = 0; i < 4; i++) {
            const int b = bloc0 + 4 * i;
            float va[4], vb[4];
            va[0] = xr[i][0].x - m0.x; va[1] = xr[i][0].y - m0.y;
            va[2] = xr[i][0].z - m0.z; va[3] = xr[i][0].w - m0.w;
            vb[0] = xr[i][1].x - m1.x; vb[1] = xr[i][1].y - m1.y;
            vb[2] = xr[i][1].z - m1.z; vb[3] = xr[i][1].w - m1.w;
            uint32_t base = abase + (uint32_t)(kq1 * 4) * ASTR + b * 128
                          + ((((uint32_t)(ep >> 2)) ^ (uint32_t)(b & 7)) << 4)
                          + (ep & 3) * 4;
            #pragma unroll
            for (int j = 0; j < 4; j++) {
                uint32_t h2 = cvt2(vb[j], va[j]);   // lo = even e
                asm volatile("st.shared.b32 [%0], %1;"
                             :: "r"(base + (uint32_t)(j * ASTR)), "r"(h2) : "memory");
            }
        }
    };

    // ---- prologue: stage A(by), prefetch x(by+NBY) ----
    ldx(by);
    stx(abase0);
    ldx(by + NBY);        // by+NBY < 512 always (by < 18)
    __syncthreads();
    int cur = 0;

    for (int bt = by; bt < 512; bt += NBY) {
        const int b0  = bt * 16;
        const uint32_t abase = cur ? abase1 : abase0;
        const uint32_t aalt  = cur ? abase0 : abase1;

        // ======= MMA: 2 k x 16 b x 32 d (reads abase) =======
        float D[2][16];
        #pragma unroll
        for (int a = 0; a < 2; a++)
            #pragma unroll
            for (int j = 0; j < 16; j++) D[a][j] = 0.f;

        #pragma unroll
        for (int kk = 0; kk < 2; kk++) {
            const int k = kq * 2 + kk;
            const uint32_t Ab = abase + (uint32_t)k * ASTR;
            const uint32_t Bb = sb + BOFF + (uint32_t)k * 8192;
            #pragma unroll
            for (int es = 0; es < 4; es++) {
                uint32_t a0, a1, a2, a3;
                uint32_t aaddr = Ab + l15 * 128
                               + ((((uint32_t)(es * 2 + lhi)) ^ (uint32_t)(l15 & 7)) << 4);
                ldm_x4(a0, a1, a2, a3, aaddr);
                const int rB = es * 16 + l15;
                #pragma unroll
                for (int ncp = 0; ncp < 2; ncp++) {
                    const int nc = dh * 4 + ncp * 2;
                    uint32_t b0r, b1r, b2r, b3r;
                    uint32_t baddr = Bb + rB * 128
                        + ((((uint32_t)(nc + lhi)) ^ (uint32_t)(rB & 7)) << 4);
                    ldm_x4t(b0r, b1r, b2r, b3r, baddr);
                    mma16816(D[kk][ncp*8+0], D[kk][ncp*8+1], D[kk][ncp*8+2], D[kk][ncp*8+3],
                             a0, a1, a2, a3, b0r, b1r);
                    mma16816(D[kk][ncp*8+4], D[kk][ncp*8+5], D[kk][ncp*8+6], D[kk][ncp*8+7],
                             a0, a1, a2, a3, b2r, b3r);
                }
            }
        }

        __syncthreads();   // sync1: MMA(cur) + prev STG reads all done

        // stage next A into the alternate buffer (xr = x(bt+NBY))
        if (bt + NBY < 512) stx(aalt);

        // ======= Dbuf write (single pass, all warps) =======
        // Dbuf row d: region = d>>5 (0 -> abase, 1 -> E), row (d&31)*1024.
        // slot16 = (bb*4 + kq>>1) ^ (d&7) ^ ((bb>>1)&1); 8B sub-slot = kq&1.
        {
            const uint32_t dreg = (dh == 0) ? abase : (sb + EOFF);
            #pragma unroll
            for (int ncl = 0; ncl < 4; ncl++) {
                #pragma unroll
                for (int j = 0; j < 4; j++) {
                    const int bb = g + ((j & 2) ? 8 : 0);
                    const int dl = ncl * 8 + tg * 2 + (j & 1);   // 0..31 in region
                    const uint32_t slot = ((uint32_t)(bb * 4 + (kq >> 1)))
                                        ^ (uint32_t)(dl & 7) ^ (uint32_t)((bb >> 1) & 1);
                    const uint32_t addr = dreg + (uint32_t)(dl * 1024) + (slot << 4)
                                        + (uint32_t)((kq & 1) * 8);
                    asm volatile("st.shared.v2.f32 [%0], {%1,%2};"
                                 :: "r"(addr),
                                    "f"(D[0][ncl*4+j]), "f"(D[1][ncl*4+j]) : "memory");
                }
            }
        }

        __syncthreads();   // sync2: stx(next) + Dbuf visible

        // ======= coalesced store (all 64 d in one pass) =======
        // o: kq2 = o&3, dl = (o>>2)&63, bb = o>>8 (0..15)
        #pragma unroll
        for (int i = 0; i < 8; i++) {
            int o   = tid + 512 * i;
            int kq2 = o & 3;
            int dl  = (o >> 2) & 63;
            int bb  = o >> 8;
            uint32_t base = (dl < 32) ? abase : (sb + EOFF);
            uint32_t slot = ((uint32_t)(bb * 4 + kq2))
                          ^ (uint32_t)(dl & 7) ^ (uint32_t)((bb >> 1) & 1);
            float4 f;
            asm volatile("ld.shared.v4.f32 {%0,%1,%2,%3}, [%4];"
                         : "=f"(f.x), "=f"(f.y), "=f"(f.z), "=f"(f.w)
                         : "r"(base + (uint32_t)((dl & 31) * 1024) + (slot << 4)));
            float* op = out + (size_t)(b0 + bb) * 8192
                      + (size_t)dl * 128 + kbase + kq2 * 4;
            *(float4*)(op) = f;
        }

        // prefetch x for the tile after next (xr free after stx above)
        if (bt + 2 * NBY < 512) ldx(bt + 2 * NBY);

        cur ^= 1;
        // STG reads of this tile's Dbuf are protected by next iteration's sync1
        // before anyone overwrites those regions.
    }
}

extern "C" void kernel_launch(void* const* d_in, const int* in_sizes, int n_in,
                              void* d_out, int out_size)
{
    const float* x  = (const float*)d_in[0];   // [8192, 64, 128]
    const float* mu = (const float*)d_in[1];   // [64, 128]
    const float* S  = (const float*)d_in[2];   // [128, 64, 64]
    float* out      = (float*)d_out;           // [8192, 64, 128]

    cudaFuncSetAttribute(cluster_norm_mma_kernel,
                         cudaFuncAttributeMaxDynamicSharedMemorySize, SMEM_BYTES);

    dim3 grid(8, NBY);
    cluster_norm_mma_kernel<<<grid, 512, SMEM_BYTES>>>(x, mu, S, out);
}

// round 15
// speedup vs baseline: 1.3008x; 1.3008x over previous
#include <cuda_runtime.h>
#include <cuda_fp16.h>
#include <cstdint>

// out[b,d,k] = sum_e S[k,d,e] * (x[b,e,k] - mu[e,k])
// B=8192, D=E=64, K=128. fp32 in/out.
// R15: KT=8, b-sub-tile 32. B-ldmatrix (the dominant, sub-tile-invariant L1
// term) is amortized over 2x the outputs; barrier rate per output halves.
// R12's proven 5-sync pipeline; warp tile 2k x 16b x 32d (4kq x 2bh x 2dh).
// smem 131KB -> ~97KB L1D remains.

#define NBY  9
#define ASTR 4112                          // per-k A stride (32 rows x 128B + 16)

static constexpr int ABUF = 8 * ASTR;      // 32896 per buffer (Dbuf needs 32768)
static constexpr int BOFF = 2 * ABUF;      // 65792
static constexpr int SMEM_BYTES = BOFF + 8 * 8192;   // 131328

__device__ __forceinline__ uint32_t cvt2(float hi, float lo) {
    uint32_t r;
    asm("cvt.rn.f16x2.f32 %0, %1, %2;" : "=r"(r) : "f"(hi), "f"(lo));
    return r;
}
__device__ __forceinline__ void ldm_x4(uint32_t& r0, uint32_t& r1, uint32_t& r2,
                                       uint32_t& r3, uint32_t addr) {
    asm volatile("ldmatrix.sync.aligned.m8n8.x4.shared.b16 {%0,%1,%2,%3}, [%4];"
                 : "=r"(r0), "=r"(r1), "=r"(r2), "=r"(r3) : "r"(addr));
}
__device__ __forceinline__ void ldm_x4t(uint32_t& r0, uint32_t& r1, uint32_t& r2,
                                        uint32_t& r3, uint32_t addr) {
    asm volatile("ldmatrix.sync.aligned.m8n8.x4.trans.shared.b16 {%0,%1,%2,%3}, [%4];"
                 : "=r"(r0), "=r"(r1), "=r"(r2), "=r"(r3) : "r"(addr));
}
__device__ __forceinline__ void mma16816(float& d0, float& d1, float& d2, float& d3,
                                         uint32_t a0, uint32_t a1, uint32_t a2, uint32_t a3,
                                         uint32_t b0, uint32_t b1) {
    asm volatile(
        "mma.sync.aligned.m16n8k16.row.col.f32.f16.f16.f32 "
        "{%0,%1,%2,%3}, {%4,%5,%6,%7}, {%8,%9}, {%0,%1,%2,%3};"
        : "+f"(d0), "+f"(d1), "+f"(d2), "+f"(d3)
        : "r"(a0), "r"(a1), "r"(a2), "r"(a3), "r"(b0), "r"(b1));
}

__global__ __launch_bounds__(512, 1)
void cluster_norm_mma_kernel(const float* __restrict__ x,
                             const float* __restrict__ mu,
                             const float* __restrict__ S,
                             float* __restrict__ out)
{
    extern __shared__ char smem[];
    const uint32_t sb = (uint32_t)__cvta_generic_to_shared(smem);
    const int tid   = threadIdx.x;
    const int lane  = tid & 31;
    const int w     = tid >> 5;
    const int kbase = blockIdx.x * 8;
    const int by    = blockIdx.y;

    // ---- S -> fp16 B tiles: Bk[e][d], rows 128B, slot ^= (e&7) ----
    #pragma unroll 4
    for (int i = 0; i < 32; i++) {
        int o  = tid + 512 * i;
        int e  = o & 63;
        int dp = (o >> 6) & 31;
        int k  = o >> 11;                  // 0..7
        const float* sp = S + (size_t)(kbase + k) * 4096 + (size_t)(dp * 2) * 64 + e;
        float s0 = sp[0];
        float s1 = sp[64];
        uint32_t h2 = cvt2(s1, s0);        // lo = even d
        uint32_t a = sb + BOFF + k * 8192 + e * 128
                   + ((((uint32_t)(dp >> 2)) ^ (uint32_t)(e & 7)) << 4) + (dp & 3) * 4;
        asm volatile("st.shared.b32 [%0], %1;" :: "r"(a), "r"(h2) : "memory");
    }

    // ---- staging thread constants + mu register preload ----
    const int kh    = tid & 1;             // k-half (k = kh*4 + j)
    const int ep    = (tid >> 1) & 31;     // e-pair
    const int bloc0 = tid >> 6;            // 0..7
    float4 m0 = *(const float4*)(mu + (size_t)(2 * ep) * 128 + kbase + kh * 4);
    float4 m1 = *(const float4*)(mu + (size_t)(2 * ep + 1) * 128 + kbase + kh * 4);

    // warp tile: kq = w&3 (2 k), bh = (w>>2)&1 (16 b), dh = w>>3 (32 d)
    const int kq  = w & 3;
    const int bh  = (w >> 2) & 1;
    const int dh  = w >> 3;
    const int l15 = lane & 15;
    const int lhi = lane >> 4;
    const int rA  = bh * 16 + l15;         // A row (b within 32)
    const int g   = lane >> 2;
    const int tg  = lane & 3;

    const uint32_t abase0 = sb;
    const uint32_t abase1 = sb + ABUF;

    float4 xr[4][2];

    auto ldx = [&](int bt) {
        const int b0 = bt * 32;
        #pragma unroll
        for (int i = 0; i < 4; i++) {
            const int b = bloc0 + 8 * i;
            const float* xp = x + (size_t)(b0 + b) * 8192 + (size_t)(2 * ep) * 128
                            + kbase + kh * 4;
            xr[i][0] = *(const float4*)(xp);        // e = 2ep
            xr[i][1] = *(const float4*)(xp + 128);  // e = 2ep+1
        }
    };
    auto stx = [&](uint32_t abase) {
        #pragma unroll
        for (int i = 0; i < 4; i++) {
            const int b = bloc0 + 8 * i;
            float va[4], vb[4];
            va[0] = xr[i][0].x - m0.x; va[1] = xr[i][0].y - m0.y;
            va[2] = xr[i][0].z - m0.z; va[3] = xr[i][0].w - m0.w;
            vb[0] = xr[i][1].x - m1.x; vb[1] = xr[i][1].y - m1.y;
            vb[2] = xr[i][1].z - m1.z; vb[3] = xr[i][1].w - m1.w;
            uint32_t base = abase + (uint32_t)(kh * 4) * ASTR + b * 128
                          + ((((uint32_t)(ep >> 2)) ^ (uint32_t)(b & 7)) << 4)
                          + (ep & 3) * 4;
            #pragma unroll
            for (int j = 0; j < 4; j++) {
                uint32_t h2 = cvt2(vb[j], va[j]);   // lo = even e
                asm volatile("st.shared.b32 [%0], %1;"
                             :: "r"(base + (uint32_t)(j * ASTR)), "r"(h2) : "memory");
            }
        }
    };

    // ---- prologue ----
    ldx(by);
    stx(abase0);
    int cur = 0;

    for (int bt = by; bt < 256; bt += NBY) {
        const int b0  = bt * 32;
        const int nxt = bt + NBY;
        const uint32_t abase = cur ? abase1 : abase0;
        const uint32_t aalt  = cur ? abase0 : abase1;

        __syncthreads();                   // A(cur) visible; prev STG reads done

        if (nxt < 256) ldx(nxt);           // global loads early (hidden by MMA)

        // ======= MMA: 2 k x 16 b x 32 d =======
        float D[2][16];
        #pragma unroll
        for (int a = 0; a < 2; a++)
            #pragma unroll
            for (int j = 0; j < 16; j++) D[a][j] = 0.f;

        #pragma unroll
        for (int kk = 0; kk < 2; kk++) {
            const int k = kq * 2 + kk;
            const uint32_t Ab = abase + (uint32_t)k * ASTR;
            const uint32_t Bb = sb + BOFF + (uint32_t)k * 8192;
            #pragma unroll
            for (int es = 0; es < 4; es++) {
                uint32_t a0, a1, a2, a3;
                uint32_t aaddr = Ab + rA * 128
                               + ((((uint32_t)(es * 2 + lhi)) ^ (uint32_t)(rA & 7)) << 4);
                ldm_x4(a0, a1, a2, a3, aaddr);
                const int rB = es * 16 + l15;
                #pragma unroll
                for (int ncp = 0; ncp < 2; ncp++) {
                    const int nc = dh * 4 + ncp * 2;
                    uint32_t b0r, b1r, b2r, b3r;
                    uint32_t baddr = Bb + rB * 128
                        + ((((uint32_t)(nc + lhi)) ^ (uint32_t)(rB & 7)) << 4);
                    ldm_x4t(b0r, b1r, b2r, b3r, baddr);
                    mma16816(D[kk][ncp*8+0], D[kk][ncp*8+1], D[kk][ncp*8+2], D[kk][ncp*8+3],
                             a0, a1, a2, a3, b0r, b1r);
                    mma16816(D[kk][ncp*8+4], D[kk][ncp*8+5], D[kk][ncp*8+6], D[kk][ncp*8+7],
                             a0, a1, a2, a3, b2r, b3r);
                }
            }
        }

        if (nxt < 256) stx(aalt);          // stage next tile into the other buffer

        __syncthreads();                   // MMA+STS(next) done; Dbuf (= abase) free

        // ======= epilogue: two 32-d passes, Dbuf = abase region =======
        // Dbuf row dl (0..31) x 1024B = 32 bb x 32B (8 k).
        // slot16 = (bb*2 + kh16) ^ (dl&6); write: kh16 = kq>>1, sub8 = kq&1.
        #pragma unroll
        for (int p = 0; p < 2; p++) {
            if (dh == p) {
                #pragma unroll
                for (int ncl = 0; ncl < 4; ncl++) {
                    #pragma unroll
                    for (int j = 0; j < 4; j++) {
                        const int bb = bh * 16 + g + ((j & 2) ? 8 : 0);
                        const int dl = ncl * 8 + tg * 2 + (j & 1);
                        const uint32_t slot = ((uint32_t)(bb * 2 + (kq >> 1)))
                                            ^ (uint32_t)(dl & 6);
                        const uint32_t addr = abase + (uint32_t)(dl * 1024) + (slot << 4)
                                            + (uint32_t)((kq & 1) * 8);
                        asm volatile("st.shared.v2.f32 [%0], {%1,%2};"
                                     :: "r"(addr),
                                        "f"(D[0][ncl*4+j]), "f"(D[1][ncl*4+j]) : "memory");
                    }
                }
            }
            __syncthreads();

            // coalesced store: o: kh16 = o&1, dl = (o>>1)&31, bb = (o>>6)&31
            #pragma unroll
            for (int i = 0; i < 4; i++) {
                int o    = tid + 512 * i;
                int kh16 = o & 1;
                int dl   = (o >> 1) & 31;
                int bb   = (o >> 6) & 31;
                uint32_t slot = ((uint32_t)(bb * 2 + kh16)) ^ (uint32_t)(dl & 6);
                float4 f;
                asm volatile("ld.shared.v4.f32 {%0,%1,%2,%3}, [%4];"
                             : "=f"(f.x), "=f"(f.y), "=f"(f.z), "=f"(f.w)
                             : "r"(abase + (uint32_t)(dl * 1024) + (slot << 4)));
                float* op = out + (size_t)(b0 + bb) * 8192
                          + (size_t)(p * 32 + dl) * 128 + kbase + kh16 * 4;
                *(float4*)(op) = f;
            }
            if (p == 0) __syncthreads();   // pass-0 reads done before pass-1 writes
        }
        cur ^= 1;
        // pass-1 reads protected by next iteration's first __syncthreads()
    }
}

extern "C" void kernel_launch(void* const* d_in, const int* in_sizes, int n_in,
                              void* d_out, int out_size)
{
    const float* x  = (const float*)d_in[0];   // [8192, 64, 128]
    const float* mu = (const float*)d_in[1];   // [64, 128]
    const float* S  = (const float*)d_in[2];   // [128, 64, 64]
    float* out      = (float*)d_out;           // [8192, 64, 128]

    cudaFuncSetAttribute(cluster_norm_mma_kernel,
                         cudaFuncAttributeMaxDynamicSharedMemorySize, SMEM_BYTES);

    dim3 grid(16, NBY);
    cluster_norm_mma_kernel<<<grid, 512, SMEM_BYTES>>>(x, mu, S, out);
}

// round 16
// speedup vs baseline: 1.5833x; 1.2172x over previous
#include <cuda_runtime.h>
#include <cuda_fp16.h>
#include <cstdint>

// out[b,d,k] = sum_e S[k,d,e] * (x[b,e,k] - mu[e,k])
// B=8192, D=E=64, K=128. fp32 in/out.
// R16 = R12 (best: 155us) + prefetch distance 2: ldx(bt+2*NBY) is issued
// right after stx(bt+NBY) consumes xr, so the LDG has the whole epilogue +
// next MMA (~5-7k cyc) to land instead of just the MMA phase (~700 cyc).
// Everything else identical to R12: KT=16, b-sub-tile 16, 512 thr,
// warp tile 4k x 16b x 16d, 5-sync pipeline, A-region Dbuf reuse.

#define NBY  18
#define ASTR 2064                         // per-k A stride (16 rows x 128B + pad)

static constexpr int ABUF  = 16 * ASTR;   // 33024 per buffer (Dbuf needs 32768)
static constexpr int BOFF  = 2 * ABUF;    // 66048
static constexpr int SMEM_BYTES = BOFF + 16 * 8192;   // 197120

__device__ __forceinline__ uint32_t cvt2(float hi, float lo) {
    uint32_t r;
    asm("cvt.rn.f16x2.f32 %0, %1, %2;" : "=r"(r) : "f"(hi), "f"(lo));
    return r;
}
__device__ __forceinline__ void ldm_x4(uint32_t& r0, uint32_t& r1, uint32_t& r2,
                                       uint32_t& r3, uint32_t addr) {
    asm volatile("ldmatrix.sync.aligned.m8n8.x4.shared.b16 {%0,%1,%2,%3}, [%4];"
                 : "=r"(r0), "=r"(r1), "=r"(r2), "=r"(r3) : "r"(addr));
}
__device__ __forceinline__ void ldm_x4t(uint32_t& r0, uint32_t& r1, uint32_t& r2,
                                        uint32_t& r3, uint32_t addr) {
    asm volatile("ldmatrix.sync.aligned.m8n8.x4.trans.shared.b16 {%0,%1,%2,%3}, [%4];"
                 : "=r"(r0), "=r"(r1), "=r"(r2), "=r"(r3) : "r"(addr));
}
__device__ __forceinline__ void mma16816(float& d0, float& d1, float& d2, float& d3,
                                         uint32_t a0, uint32_t a1, uint32_t a2, uint32_t a3,
                                         uint32_t b0, uint32_t b1) {
    asm volatile(
        "mma.sync.aligned.m16n8k16.row.col.f32.f16.f16.f32 "
        "{%0,%1,%2,%3}, {%4,%5,%6,%7}, {%8,%9}, {%0,%1,%2,%3};"
        : "+f"(d0), "+f"(d1), "+f"(d2), "+f"(d3)
        : "r"(a0), "r"(a1), "r"(a2), "r"(a3), "r"(b0), "r"(b1));
}

__global__ __launch_bounds__(512, 1)
void cluster_norm_mma_kernel(const float* __restrict__ x,
                             const float* __restrict__ mu,
                             const float* __restrict__ S,
                             float* __restrict__ out)
{
    extern __shared__ char smem[];
    const uint32_t sb = (uint32_t)__cvta_generic_to_shared(smem);
    const int tid   = threadIdx.x;
    const int lane  = tid & 31;
    const int w     = tid >> 5;
    const int kbase = blockIdx.x * 16;
    const int by    = blockIdx.y;

    // ---- S -> fp16 B tiles: Bk[e][d], rows 128B, slot ^= (e&7) ----
    #pragma unroll 4
    for (int i = 0; i < 64; i++) {
        int o  = tid + 512 * i;
        int e  = o & 63;
        int dp = (o >> 6) & 31;
        int k  = o >> 11;                 // 0..15
        const float* sp = S + (size_t)(kbase + k) * 4096 + (size_t)(dp * 2) * 64 + e;
        float s0 = sp[0];
        float s1 = sp[64];
        uint32_t h2 = cvt2(s1, s0);       // lo = even d
        uint32_t a = sb + BOFF + k * 8192 + e * 128
                   + ((((uint32_t)(dp >> 2)) ^ (uint32_t)(e & 7)) << 4) + (dp & 3) * 4;
        asm volatile("st.shared.b32 [%0], %1;" :: "r"(a), "r"(h2) : "memory");
    }

    // ---- phase-1 thread constants + mu register preload ----
    // kq1 = tid&3 (k-quad), ep = (tid>>2)&31 (e-pair), bloc0 = tid>>7 (0..3)
    const int kq1   = tid & 3;
    const int ep    = (tid >> 2) & 31;
    const int bloc0 = tid >> 7;
    float4 m0 = *(const float4*)(mu + (size_t)(2 * ep) * 128 + kbase + kq1 * 4);
    float4 m1 = *(const float4*)(mu + (size_t)(2 * ep + 1) * 128 + kbase + kq1 * 4);

    // warp tile: kq = w&3 (4 k), dh = (w>>2)&3 (16 d), all 16 b
    const int kq  = w & 3;
    const int dh  = (w >> 2) & 3;
    const int l15 = lane & 15;
    const int lhi = lane >> 4;
    const int g   = lane >> 2;
    const int tg  = lane & 3;

    const uint32_t abase0 = sb;
    const uint32_t abase1 = sb + ABUF;

    float4 xr[4][2];

    // load sub-tile bt's x slice into registers
    auto ldx = [&](int bt) {
        const int b0 = bt * 16;
        #pragma unroll
        for (int i = 0; i < 4; i++) {
            const int b = bloc0 + 4 * i;
            const float* xp = x + (size_t)(b0 + b) * 8192 + (size_t)(2 * ep) * 128
                            + kbase + kq1 * 4;
            xr[i][0] = *(const float4*)(xp);        // e = 2ep
            xr[i][1] = *(const float4*)(xp + 128);  // e = 2ep+1
        }
    };
    // convert registers -> fp16 A tiles at abase
    auto stx = [&](uint32_t abase) {
        #pragma unroll
        for (int i = 0; i < 4; i++) {
            const int b = bloc0 + 4 * i;
            float va[4], vb[4];
            va[0] = xr[i][0].x - m0.x; va[1] = xr[i][0].y - m0.y;
            va[2] = xr[i][0].z - m0.z; va[3] = xr[i][0].w - m0.w;
            vb[0] = xr[i][1].x - m1.x; vb[1] = xr[i][1].y - m1.y;
            vb[2] = xr[i][1].z - m1.z; vb[3] = xr[i][1].w - m1.w;
            uint32_t base = abase + (uint32_t)(kq1 * 4) * ASTR + b * 128
                          + ((((uint32_t)(ep >> 2)) ^ (uint32_t)(b & 7)) << 4)
                          + (ep & 3) * 4;
            #pragma unroll
            for (int j = 0; j < 4; j++) {
                uint32_t h2 = cvt2(vb[j], va[j]);   // lo = even e
                asm volatile("st.shared.b32 [%0], %1;"
                             :: "r"(base + (uint32_t)(j * ASTR)), "r"(h2) : "memory");
            }
        }
    };

    // ---- prologue: stage A(by), then prefetch x(by+NBY) ----
    ldx(by);
    stx(abase0);
    ldx(by + NBY);                        // by+NBY < 512 always (by < 18)
    int cur = 0;

    for (int bt = by; bt < 512; bt += NBY) {
        const int b0  = bt * 16;
        const int nxt = bt + NBY;
        const uint32_t abase = cur ? abase1 : abase0;
        const uint32_t aalt  = cur ? abase0 : abase1;

        __syncthreads();                  // A(cur) visible; prev epilogue reads done

        // ======= MMA: 4 k x 16 b x 16 d =======
        float D[4][8];
        #pragma unroll
        for (int a = 0; a < 4; a++)
            #pragma unroll
            for (int j = 0; j < 8; j++) D[a][j] = 0.f;

        #pragma unroll
        for (int kk = 0; kk < 4; kk++) {
            const int k = kq * 4 + kk;
            const uint32_t Ab = abase + (uint32_t)k * ASTR;
            #pragma unroll
            for (int es = 0; es < 4; es++) {
                uint32_t a0, a1, a2, a3;
                uint32_t aaddr = Ab + l15 * 128
                               + ((((uint32_t)(es * 2 + lhi)) ^ (uint32_t)(l15 & 7)) << 4);
                ldm_x4(a0, a1, a2, a3, aaddr);
                const int rB = es * 16 + l15;
                uint32_t b0r, b1r, b2r, b3r;
                uint32_t baddr = sb + BOFF + (uint32_t)k * 8192 + rB * 128
                               + ((((uint32_t)(dh * 2 + lhi)) ^ (uint32_t)(rB & 7)) << 4);
                ldm_x4t(b0r, b1r, b2r, b3r, baddr);
                mma16816(D[kk][0], D[kk][1], D[kk][2], D[kk][3],
                         a0, a1, a2, a3, b0r, b1r);
                mma16816(D[kk][4], D[kk][5], D[kk][6], D[kk][7],
                         a0, a1, a2, a3, b2r, b3r);
            }
        }

        if (nxt < 512) stx(aalt);         // stage next tile (consumes xr)
        if (bt + 2 * NBY < 512) ldx(bt + 2 * NBY);  // refill xr: lands during
                                                    // epilogue + next MMA

        __syncthreads();                  // MMA+STS(next) done; Dbuf (= abase) free

        // ======= epilogue: two 32-d passes, Dbuf = abase region =======
        // Dbuf row dl (0..31) x 1024B; slot16 = (bb*4+kq) ^ (dl&7) ^ ((bb>>1)&1)
        #pragma unroll
        for (int p = 0; p < 2; p++) {
            if ((dh >> 1) == p) {
                const int dhl = dh & 1;
                #pragma unroll
                for (int ncl = 0; ncl < 2; ncl++) {
                    #pragma unroll
                    for (int j = 0; j < 4; j++) {
                        const int bb = g + ((j & 2) ? 8 : 0);
                        const int dl = dhl * 16 + ncl * 8 + tg * 2 + (j & 1);
                        const uint32_t slot = ((uint32_t)(bb * 4 + kq))
                                            ^ (uint32_t)(dl & 7) ^ (uint32_t)((bb >> 1) & 1);
                        const uint32_t addr = abase + (uint32_t)(dl * 1024) + (slot << 4);
                        asm volatile("st.shared.v4.f32 [%0], {%1,%2,%3,%4};"
                                     :: "r"(addr),
                                        "f"(D[0][ncl*4+j]), "f"(D[1][ncl*4+j]),
                                        "f"(D[2][ncl*4+j]), "f"(D[3][ncl*4+j]) : "memory");
                    }
                }
            }
            __syncthreads();

            // coalesced store: o: kq2 = o&3, dl = (o>>2)&31, bb = (o>>7)&15
            #pragma unroll
            for (int i = 0; i < 4; i++) {
                int o   = tid + 512 * i;
                int kq2 = o & 3;
                int dl  = (o >> 2) & 31;
                int bb  = (o >> 7) & 15;
                uint32_t slot = ((uint32_t)(bb * 4 + kq2))
                              ^ (uint32_t)(dl & 7) ^ (uint32_t)((bb >> 1) & 1);
                float4 f;
                asm volatile("ld.shared.v4.f32 {%0,%1,%2,%3}, [%4];"
                             : "=f"(f.x), "=f"(f.y), "=f"(f.z), "=f"(f.w)
                             : "r"(abase + (uint32_t)(dl * 1024) + (slot << 4)));
                float* op = out + (size_t)(b0 + bb) * 8192
                          + (size_t)(p * 32 + dl) * 128 + kbase + kq2 * 4;
                *(float4*)(op) = f;
            }
            if (p == 0) __syncthreads();  // pass-0 reads done before pass-1 writes
        }
        cur ^= 1;
        // pass-1 reads protected by next iteration's first __syncthreads()
    }
}

extern "C" void kernel_launch(void* const* d_in, const int* in_sizes, int n_in,
                              void* d_out, int out_size)
{
    const float* x  = (const float*)d_in[0];   // [8192, 64, 128]
    const float* mu = (const float*)d_in[1];   // [64, 128]
    const float* S  = (const float*)d_in[2];   // [128, 64, 64]
    float* out      = (float*)d_out;           // [8192, 64, 128]

    cudaFuncSetAttribute(cluster_norm_mma_kernel,
                         cudaFuncAttributeMaxDynamicSharedMemorySize, SMEM_BYTES);

    dim3 grid(8, NBY);
    cluster_norm_mma_kernel<<<grid, 512, SMEM_BYTES>>>(x, mu, S, out);
}